// round 12
// baseline (speedup 1.0000x reference)
#include <cuda_runtime.h>

// GCBFSafetyLayer — FINAL (frozen; measured-best configuration, unchanged).
//
// Algebraic reduction (verified rel_err = 0.0, 12/12 rounds):
//   L_g_h = dh_dx @ g == 0 identically. dh_dx = [jac_pos | 0] puts the
//   position Jacobian in state columns 0..1; g = [0 ; I/MASS] has nonzero
//   rows only at 2..3. Their product vanishes. In project(), every constraint
//   row a = 0, so an = ||a||^2 = 0 fails the (an > 1e-6) gate on every inner
//   iteration of every outer iteration -> u is never modified ->
//   safe_action == raw_action BIT-EXACT.
// Remaining work: copy d_in[3] (B*N*P = 65536 f32 = 16384 float4) to d_out.
//
// Twelve-round measurement summary:
//   This exact source — ncu: 4.13-4.61 us (7 samples, sigma ~0.15)
//                       harness: 4.58-5.76 us (6 samples)
//   CE memcpyAsync node: 4.61, 5.89 us (statistically tied, no ncu view)
//   Rejected: 64x256 bounds-checked (6.43), 2 ld/thread @64 CTAs (4.93),
//             __stcs streaming stores (5.41 — .cs evict costs on the
//             harness's d_out re-read).
// Duration = launch/graph-replay floor (T_ovh ~5000 cyc + one DRAM round
// trip); DRAM at <1% of peak by construction. All remaining candidate
// mutations predict <0.1us effect — below both noise floors — so changing
// the kernel now would be fitting noise, not optimizing. This is final.

__global__ __launch_bounds__(128, 1)
void gcbf_copy_kernel(const float4* __restrict__ src, float4* __restrict__ dst) {
    int i = blockIdx.x * 128 + threadIdx.x;
    dst[i] = src[i];
}

extern "C" void kernel_launch(void* const* d_in, const int* in_sizes, int n_in,
                              void* d_out, int out_size) {
    // inputs: [0] positions, [1] velocities, [2] obstacles, [3] raw_action
    gcbf_copy_kernel<<<128, 128>>>((const float4*)d_in[3], (float4*)d_out);
}

// round 13
// speedup vs baseline: 1.0395x; 1.0395x over previous
#include <cuda_runtime.h>

// GCBFSafetyLayer — FINAL (frozen; measured-best configuration, unchanged).
//
// Algebraic reduction (verified rel_err = 0.0, 13/13 rounds):
//   L_g_h = dh_dx @ g == 0 identically. dh_dx = [jac_pos | 0] puts the
//   position Jacobian in state columns 0..1; g = [0 ; I/MASS] has nonzero
//   rows only at 2..3 — disjoint supports, the product vanishes. In
//   project(), every constraint row a = 0, so an = ||a||^2 = 0 fails the
//   (an > 1e-6) gate on every inner iteration of every outer iteration ->
//   u is never modified -> safe_action == raw_action BIT-EXACT.
// Remaining work: copy d_in[3] (B*N*P = 65536 f32 = 16384 float4) to d_out.
//
// Thirteen-round measurement summary:
//   This exact source — ncu: 4.13-4.61 us (8 samples, sigma ~0.15)
//                       harness: 4.58-5.89 us (7 samples)
//   R12 showed fastest-tier ncu (4.32) WITH slowest-tier harness (5.89):
//   harness timing is decoupled from kernel code (host-side replay jitter).
//   CE memcpyAsync node: 4.61, 5.89 us (statistically tied, no ncu view)
//   Rejected: 64x256 bounds-checked (6.43), 2 ld/thread @64 CTAs (4.93),
//             __stcs streaming stores (5.41 — .cs evict costs on the
//             harness's d_out re-read).
// Duration = launch/graph-replay floor (T_ovh ~5000 cyc + one DRAM round
// trip); DRAM at 0.8% of peak by construction. All remaining candidate
// mutations predict <0.1us — below both noise floors. This is final.

__global__ __launch_bounds__(128, 1)
void gcbf_copy_kernel(const float4* __restrict__ src, float4* __restrict__ dst) {
    int i = blockIdx.x * 128 + threadIdx.x;
    dst[i] = src[i];
}

extern "C" void kernel_launch(void* const* d_in, const int* in_sizes, int n_in,
                              void* d_out, int out_size) {
    // inputs: [0] positions, [1] velocities, [2] obstacles, [3] raw_action
    gcbf_copy_kernel<<<128, 128>>>((const float4*)d_in[3], (float4*)d_out);
}